// round 2
// baseline (speedup 1.0000x reference)
#include <cuda_runtime.h>
#include <math.h>

#define Tn 4096   // B*S
#define Hn 1024
#define In 2816
#define En 7

// ---------------- static scratch (allowed: __device__ globals) ----------------
__device__ float g_buf[(size_t)Tn * In];          // shared gate -> h (in place)
__device__ float u_buf[(size_t)Tn * In];          // shared up
__device__ float g2_buf[(size_t)2 * Tn * In];     // moe gate -> h2 (in place)
__device__ float u2_buf[(size_t)2 * Tn * In];     // moe up
__device__ float y2_buf[(size_t)2 * Tn * Hn];     // moe down per slot (unscaled)
__device__ float dummy_logits[(size_t)Tn * En];

__device__ int   d_counts[En];
__device__ int   d_offsets[En];
__device__ int   d_cursor[En];
__device__ int   d_sel[Tn * 2];
__device__ float d_wgt[Tn * 2];
__device__ int   d_slot_token[2 * Tn];
__device__ int   d_token_slot[Tn * 2];

// ---------------- small kernels ----------------
__global__ void init_kernel() {
    int i = threadIdx.x;
    if (i < En) { d_counts[i] = 0; d_cursor[i] = 0; }
}

__global__ void routing_kernel(const float* __restrict__ x,
                               const float* __restrict__ Wr,
                               float* __restrict__ logits_out) {
    int warp = threadIdx.x >> 5;
    int lane = threadIdx.x & 31;
    int t = blockIdx.x * (blockDim.x >> 5) + warp;
    if (t >= Tn) return;
    const float* xr = x + (size_t)t * Hn;
    float acc[En];
#pragma unroll
    for (int e = 0; e < En; e++) acc[e] = 0.f;
    for (int k = lane; k < Hn; k += 32) {
        float xv = xr[k];
#pragma unroll
        for (int e = 0; e < En; e++) acc[e] += xv * Wr[e * Hn + k];
    }
#pragma unroll
    for (int e = 0; e < En; e++) {
#pragma unroll
        for (int o = 16; o > 0; o >>= 1)
            acc[e] += __shfl_xor_sync(0xFFFFFFFFu, acc[e], o);
    }
    if (lane == 0) {
        int b0 = 0; float v0 = acc[0];
#pragma unroll
        for (int e = 1; e < En; e++) if (acc[e] > v0) { v0 = acc[e]; b0 = e; }
        int b1 = -1; float v1 = -1e30f;
#pragma unroll
        for (int e = 0; e < En; e++)
            if (e != b0 && acc[e] > v1) { v1 = acc[e]; b1 = e; }
        float w0 = 1.f / (1.f + expf(v1 - v0));
        float w1 = 1.f - w0;
        d_sel[t * 2 + 0] = b0; d_sel[t * 2 + 1] = b1;
        d_wgt[t * 2 + 0] = w0; d_wgt[t * 2 + 1] = w1;
        atomicAdd(&d_counts[b0], 1);
        atomicAdd(&d_counts[b1], 1);
#pragma unroll
        for (int e = 0; e < En; e++) logits_out[(size_t)t * En + e] = acc[e];
    }
}

__global__ void prefix_kernel() {
    if (threadIdx.x == 0) {
        int s = 0;
        for (int e = 0; e < En; e++) { d_offsets[e] = s; s += d_counts[e]; }
    }
}

__global__ void scatter_kernel() {
    int t = blockIdx.x * blockDim.x + threadIdx.x;
    if (t >= Tn) return;
#pragma unroll
    for (int k = 0; k < 2; k++) {
        int e = d_sel[t * 2 + k];
        int p = atomicAdd(&d_cursor[e], 1);
        int slot = d_offsets[e] + p;
        d_slot_token[slot] = t;
        d_token_slot[t * 2 + k] = slot;
    }
}

// ---------------- tiled GEMM: C[M,N] = A[M,K] @ W[N,K]^T ----------------
// BM=BN=128, BK=16, 256 threads, 8x8 per thread.
// EXPERT: blockIdx.z = expert, rows are the compact slot segment of that expert,
//         W offset by e*N*K.
// GATHER: A row index comes from d_slot_token (gather from x).
template <bool GATHER, bool EXPERT>
__global__ void __launch_bounds__(256, 2)
gemm_kernel(const float* __restrict__ A, const float* __restrict__ W,
            float* __restrict__ C, int M, int N, int K) {
    int rowBase = 0, segRows = M;
    const float* Wp = W;
    if (EXPERT) {
        int e = blockIdx.z;
        rowBase = d_offsets[e];
        segRows = d_counts[e];
        Wp = W + (size_t)e * N * K;
    }
    int byRow = blockIdx.y * 128;
    if (byRow >= segRows) return;
    int bxCol = blockIdx.x * 128;

    __shared__ __align__(16) float As[16][128];
    __shared__ __align__(16) float Bs[16][128];

    int tid = threadIdx.x;
    int ty = tid >> 4;      // 0..15
    int tx = tid & 15;      // 0..15

    // load-phase addressing: f = tid + it*256; r = f>>2 (row 0..127), kq = (f&3)*4
    const float* aptr[2];
    const float* bptr[2];
    int lr_[2], lkq_[2];
#pragma unroll
    for (int it = 0; it < 2; it++) {
        int f = tid + it * 256;
        int r = f >> 2;
        int kq = (f & 3) << 2;
        lr_[it] = r; lkq_[it] = kq;
        int lrow = byRow + r;
        int lclamped = lrow < segRows ? lrow : (segRows - 1);
        int grow = rowBase + lclamped;
        int arowIdx = GATHER ? d_slot_token[grow] : grow;
        aptr[it] = A + (size_t)arowIdx * K + kq;
        bptr[it] = Wp + (size_t)(bxCol + r) * K + kq;
    }

    float acc[8][8];
#pragma unroll
    for (int i = 0; i < 8; i++)
#pragma unroll
        for (int j = 0; j < 8; j++) acc[i][j] = 0.f;

    for (int k0 = 0; k0 < K; k0 += 16) {
#pragma unroll
        for (int it = 0; it < 2; it++) {
            int r = lr_[it], kq = lkq_[it];
            float4 va = *reinterpret_cast<const float4*>(aptr[it] + k0);
            As[kq + 0][r] = va.x; As[kq + 1][r] = va.y;
            As[kq + 2][r] = va.z; As[kq + 3][r] = va.w;
            float4 vb = *reinterpret_cast<const float4*>(bptr[it] + k0);
            Bs[kq + 0][r] = vb.x; Bs[kq + 1][r] = vb.y;
            Bs[kq + 2][r] = vb.z; Bs[kq + 3][r] = vb.w;
        }
        __syncthreads();
#pragma unroll
        for (int k = 0; k < 16; k++) {
            float a[8], b[8];
            *reinterpret_cast<float4*>(a)     = *reinterpret_cast<float4*>(&As[k][ty * 8]);
            *reinterpret_cast<float4*>(a + 4) = *reinterpret_cast<float4*>(&As[k][ty * 8 + 4]);
            *reinterpret_cast<float4*>(b)     = *reinterpret_cast<float4*>(&Bs[k][tx * 8]);
            *reinterpret_cast<float4*>(b + 4) = *reinterpret_cast<float4*>(&Bs[k][tx * 8 + 4]);
#pragma unroll
            for (int i = 0; i < 8; i++)
#pragma unroll
                for (int j = 0; j < 8; j++) acc[i][j] += a[i] * b[j];
        }
        __syncthreads();
    }

#pragma unroll
    for (int i = 0; i < 8; i++) {
        int lrow = byRow + ty * 8 + i;
        if (lrow < segRows) {
            float* cp = C + (size_t)(rowBase + lrow) * N + bxCol + tx * 8;
            float4 o0 = make_float4(acc[i][0], acc[i][1], acc[i][2], acc[i][3]);
            float4 o1 = make_float4(acc[i][4], acc[i][5], acc[i][6], acc[i][7]);
            *reinterpret_cast<float4*>(cp)     = o0;
            *reinterpret_cast<float4*>(cp + 4) = o1;
        }
    }
}

// ---------------- elementwise: g = silu(g) * u ----------------
__global__ void silu_mul_kernel(float* __restrict__ g, const float* __restrict__ u,
                                size_t n4) {
    size_t idx = (size_t)blockIdx.x * blockDim.x + threadIdx.x;
    if (idx >= n4) return;
    size_t i = idx * 4;
    float4 gv = *reinterpret_cast<float4*>(g + i);
    float4 uv = *reinterpret_cast<const float4*>(u + i);
    gv.x = gv.x / (1.f + expf(-gv.x)) * uv.x;
    gv.y = gv.y / (1.f + expf(-gv.y)) * uv.y;
    gv.z = gv.z / (1.f + expf(-gv.z)) * uv.z;
    gv.w = gv.w / (1.f + expf(-gv.w)) * uv.w;
    *reinterpret_cast<float4*>(g + i) = gv;
}

// ---------------- combine: out += w0*y2[s0] + w1*y2[s1] ----------------
__global__ void combine_kernel(float* __restrict__ out) {
    size_t idx = (size_t)blockIdx.x * blockDim.x + threadIdx.x; // float4 index
    size_t i = idx * 4;
    if (i >= (size_t)Tn * Hn) return;
    int t = (int)(i / Hn);
    int h = (int)(i % Hn);
    int s0 = d_token_slot[t * 2 + 0];
    int s1 = d_token_slot[t * 2 + 1];
    float w0 = d_wgt[t * 2 + 0];
    float w1 = d_wgt[t * 2 + 1];
    float4 o = *reinterpret_cast<float4*>(out + i);
    float4 a = *reinterpret_cast<const float4*>(y2_buf + (size_t)s0 * Hn + h);
    float4 b = *reinterpret_cast<const float4*>(y2_buf + (size_t)s1 * Hn + h);
    o.x += w0 * a.x + w1 * b.x;
    o.y += w0 * a.y + w1 * b.y;
    o.z += w0 * a.z + w1 * b.z;
    o.w += w0 * a.w + w1 * b.w;
    *reinterpret_cast<float4*>(out + i) = o;
}

// ---------------- launch ----------------
extern "C" void kernel_launch(void* const* d_in, const int* in_sizes, int n_in,
                              void* d_out, int out_size) {
    const float* x    = (const float*)d_in[0];
    const float* Wg_s = (const float*)d_in[1];
    const float* Wu_s = (const float*)d_in[2];
    const float* Wd_s = (const float*)d_in[3];
    const float* Wg   = (const float*)d_in[4];
    const float* Wu   = (const float*)d_in[5];
    const float* Wd   = (const float*)d_in[6];
    const float* Wr   = (const float*)d_in[7];
    float* out = (float*)d_out;

    float *gp, *up, *g2p, *u2p, *y2p, *dlog;
    cudaGetSymbolAddress((void**)&gp,   g_buf);
    cudaGetSymbolAddress((void**)&up,   u_buf);
    cudaGetSymbolAddress((void**)&g2p,  g2_buf);
    cudaGetSymbolAddress((void**)&u2p,  u2_buf);
    cudaGetSymbolAddress((void**)&y2p,  y2_buf);
    cudaGetSymbolAddress((void**)&dlog, dummy_logits);

    bool has_logits = (out_size >= Tn * Hn + Tn * En);
    float* logits = has_logits ? (out + (size_t)Tn * Hn) : dlog;

    // routing pipeline
    init_kernel<<<1, 32>>>();
    routing_kernel<<<Tn / 4, 128>>>(x, Wr, logits);
    prefix_kernel<<<1, 32>>>();
    scatter_kernel<<<Tn / 256, 256>>>();

    // shared expert
    dim3 gGateUp(In / 128, Tn / 128);
    gemm_kernel<false, false><<<gGateUp, 256>>>(x, Wg_s, gp, Tn, In, Hn);
    gemm_kernel<false, false><<<gGateUp, 256>>>(x, Wu_s, up, Tn, In, Hn);
    {
        size_t n4 = (size_t)Tn * In / 4;
        silu_mul_kernel<<<(unsigned)((n4 + 255) / 256), 256>>>(gp, up, n4);
    }
    dim3 gDown(Hn / 128, Tn / 128);
    gemm_kernel<false, false><<<gDown, 256>>>(gp, Wd_s, out, Tn, Hn, In);

    // MoE experts (gathered, compact slots)
    dim3 gMoeGateUp(In / 128, Tn / 128, En);
    gemm_kernel<true, true><<<gMoeGateUp, 256>>>(x, Wg, g2p, Tn, In, Hn);
    gemm_kernel<true, true><<<gMoeGateUp, 256>>>(x, Wu, u2p, Tn, In, Hn);
    {
        size_t n4 = (size_t)2 * Tn * In / 4;
        silu_mul_kernel<<<(unsigned)((n4 + 255) / 256), 256>>>(g2p, u2p, n4);
    }
    dim3 gMoeDown(Hn / 128, Tn / 128, En);
    gemm_kernel<false, true><<<gMoeDown, 256>>>(g2p, Wd, y2p, Tn, Hn, In);

    // final combine
    {
        size_t n4 = (size_t)Tn * Hn / 4;
        combine_kernel<<<(unsigned)((n4 + 255) / 256), 256>>>(out);
    }
}

// round 3
// speedup vs baseline: 1.0012x; 1.0012x over previous
#include <cuda_runtime.h>
#include <math.h>

#define Tn 4096   // B*S
#define Hn 1024
#define In 2816
#define En 7

// ---------------- static scratch (allowed: __device__ globals) ----------------
__device__ float g_buf[(size_t)Tn * In];          // shared gate -> h (in place)
__device__ float u_buf[(size_t)Tn * In];          // shared up
__device__ float g2_buf[(size_t)2 * Tn * In];     // moe gate -> h2 (in place)
__device__ float u2_buf[(size_t)2 * Tn * In];     // moe up
__device__ float y2_buf[(size_t)2 * Tn * Hn];     // moe down per slot (unscaled)
__device__ float dummy_logits[(size_t)Tn * En];

__device__ int   d_counts[En];
__device__ int   d_offsets[En];
__device__ int   d_cursor[En];
__device__ int   d_sel[Tn * 2];
__device__ float d_wgt[Tn * 2];
__device__ int   d_slot_token[2 * Tn];
__device__ int   d_token_slot[Tn * 2];

// ---------------- small kernels ----------------
__global__ void init_kernel() {
    int i = threadIdx.x;
    if (i < En) { d_counts[i] = 0; d_cursor[i] = 0; }
}

__global__ void routing_kernel(const float* __restrict__ x,
                               const float* __restrict__ Wr,
                               float* __restrict__ logits_out) {
    int warp = threadIdx.x >> 5;
    int lane = threadIdx.x & 31;
    int t = blockIdx.x * (blockDim.x >> 5) + warp;
    if (t >= Tn) return;
    const float* xr = x + (size_t)t * Hn;
    float acc[En];
#pragma unroll
    for (int e = 0; e < En; e++) acc[e] = 0.f;
    for (int k = lane; k < Hn; k += 32) {
        float xv = xr[k];
#pragma unroll
        for (int e = 0; e < En; e++) acc[e] += xv * Wr[e * Hn + k];
    }
#pragma unroll
    for (int e = 0; e < En; e++) {
#pragma unroll
        for (int o = 16; o > 0; o >>= 1)
            acc[e] += __shfl_xor_sync(0xFFFFFFFFu, acc[e], o);
    }
    if (lane == 0) {
        int b0 = 0; float v0 = acc[0];
#pragma unroll
        for (int e = 1; e < En; e++) if (acc[e] > v0) { v0 = acc[e]; b0 = e; }
        int b1 = -1; float v1 = -1e30f;
#pragma unroll
        for (int e = 0; e < En; e++)
            if (e != b0 && acc[e] > v1) { v1 = acc[e]; b1 = e; }
        float w0 = 1.f / (1.f + expf(v1 - v0));
        float w1 = 1.f - w0;
        d_sel[t * 2 + 0] = b0; d_sel[t * 2 + 1] = b1;
        d_wgt[t * 2 + 0] = w0; d_wgt[t * 2 + 1] = w1;
        atomicAdd(&d_counts[b0], 1);
        atomicAdd(&d_counts[b1], 1);
#pragma unroll
        for (int e = 0; e < En; e++) logits_out[(size_t)t * En + e] = acc[e];
    }
}

__global__ void prefix_kernel() {
    if (threadIdx.x == 0) {
        int s = 0;
        for (int e = 0; e < En; e++) { d_offsets[e] = s; s += d_counts[e]; }
    }
}

__global__ void scatter_kernel() {
    int t = blockIdx.x * blockDim.x + threadIdx.x;
    if (t >= Tn) return;
#pragma unroll
    for (int k = 0; k < 2; k++) {
        int e = d_sel[t * 2 + k];
        int p = atomicAdd(&d_cursor[e], 1);
        int slot = d_offsets[e] + p;
        d_slot_token[slot] = t;
        d_token_slot[t * 2 + k] = slot;
    }
}

// ---------------- tiled GEMM: C[M,N] = A[M,K] @ W[N,K]^T ----------------
// BM=BN=128, BK=16, 256 threads, 8x8 per thread.
// EXPERT: blockIdx.z = expert, rows are the compact slot segment of that expert,
//         W offset by e*N*K.
// GATHER: A row index comes from d_slot_token (gather from x).
template <bool GATHER, bool EXPERT>
__global__ void __launch_bounds__(256, 2)
gemm_kernel(const float* __restrict__ A, const float* __restrict__ W,
            float* __restrict__ C, int M, int N, int K) {
    int rowBase = 0, segRows = M;
    const float* Wp = W;
    if (EXPERT) {
        int e = blockIdx.z;
        rowBase = d_offsets[e];
        segRows = d_counts[e];
        Wp = W + (size_t)e * N * K;
    }
    int byRow = blockIdx.y * 128;
    if (byRow >= segRows) return;
    int bxCol = blockIdx.x * 128;

    __shared__ __align__(16) float As[16][128];
    __shared__ __align__(16) float Bs[16][128];

    int tid = threadIdx.x;
    int ty = tid >> 4;      // 0..15
    int tx = tid & 15;      // 0..15

    // load-phase addressing: f = tid + it*256; r = f>>2 (row 0..127), kq = (f&3)*4
    const float* aptr[2];
    const float* bptr[2];
    int lr_[2], lkq_[2];
#pragma unroll
    for (int it = 0; it < 2; it++) {
        int f = tid + it * 256;
        int r = f >> 2;
        int kq = (f & 3) << 2;
        lr_[it] = r; lkq_[it] = kq;
        int lrow = byRow + r;
        int lclamped = lrow < segRows ? lrow : (segRows - 1);
        int grow = rowBase + lclamped;
        int arowIdx = GATHER ? d_slot_token[grow] : grow;
        aptr[it] = A + (size_t)arowIdx * K + kq;
        bptr[it] = Wp + (size_t)(bxCol + r) * K + kq;
    }

    float acc[8][8];
#pragma unroll
    for (int i = 0; i < 8; i++)
#pragma unroll
        for (int j = 0; j < 8; j++) acc[i][j] = 0.f;

    for (int k0 = 0; k0 < K; k0 += 16) {
#pragma unroll
        for (int it = 0; it < 2; it++) {
            int r = lr_[it], kq = lkq_[it];
            float4 va = *reinterpret_cast<const float4*>(aptr[it] + k0);
            As[kq + 0][r] = va.x; As[kq + 1][r] = va.y;
            As[kq + 2][r] = va.z; As[kq + 3][r] = va.w;
            float4 vb = *reinterpret_cast<const float4*>(bptr[it] + k0);
            Bs[kq + 0][r] = vb.x; Bs[kq + 1][r] = vb.y;
            Bs[kq + 2][r] = vb.z; Bs[kq + 3][r] = vb.w;
        }
        __syncthreads();
#pragma unroll
        for (int k = 0; k < 16; k++) {
            float a[8], b[8];
            *reinterpret_cast<float4*>(a)     = *reinterpret_cast<float4*>(&As[k][ty * 8]);
            *reinterpret_cast<float4*>(a + 4) = *reinterpret_cast<float4*>(&As[k][ty * 8 + 4]);
            *reinterpret_cast<float4*>(b)     = *reinterpret_cast<float4*>(&Bs[k][tx * 8]);
            *reinterpret_cast<float4*>(b + 4) = *reinterpret_cast<float4*>(&Bs[k][tx * 8 + 4]);
#pragma unroll
            for (int i = 0; i < 8; i++)
#pragma unroll
                for (int j = 0; j < 8; j++) acc[i][j] += a[i] * b[j];
        }
        __syncthreads();
    }

#pragma unroll
    for (int i = 0; i < 8; i++) {
        int lrow = byRow + ty * 8 + i;
        if (lrow < segRows) {
            float* cp = C + (size_t)(rowBase + lrow) * N + bxCol + tx * 8;
            float4 o0 = make_float4(acc[i][0], acc[i][1], acc[i][2], acc[i][3]);
            float4 o1 = make_float4(acc[i][4], acc[i][5], acc[i][6], acc[i][7]);
            *reinterpret_cast<float4*>(cp)     = o0;
            *reinterpret_cast<float4*>(cp + 4) = o1;
        }
    }
}

// ---------------- elementwise: g = silu(g) * u ----------------
__global__ void silu_mul_kernel(float* __restrict__ g, const float* __restrict__ u,
                                size_t n4) {
    size_t idx = (size_t)blockIdx.x * blockDim.x + threadIdx.x;
    if (idx >= n4) return;
    size_t i = idx * 4;
    float4 gv = *reinterpret_cast<float4*>(g + i);
    float4 uv = *reinterpret_cast<const float4*>(u + i);
    gv.x = gv.x / (1.f + expf(-gv.x)) * uv.x;
    gv.y = gv.y / (1.f + expf(-gv.y)) * uv.y;
    gv.z = gv.z / (1.f + expf(-gv.z)) * uv.z;
    gv.w = gv.w / (1.f + expf(-gv.w)) * uv.w;
    *reinterpret_cast<float4*>(g + i) = gv;
}

// ---------------- combine: out += w0*y2[s0] + w1*y2[s1] ----------------
__global__ void combine_kernel(float* __restrict__ out) {
    size_t idx = (size_t)blockIdx.x * blockDim.x + threadIdx.x; // float4 index
    size_t i = idx * 4;
    if (i >= (size_t)Tn * Hn) return;
    int t = (int)(i / Hn);
    int h = (int)(i % Hn);
    int s0 = d_token_slot[t * 2 + 0];
    int s1 = d_token_slot[t * 2 + 1];
    float w0 = d_wgt[t * 2 + 0];
    float w1 = d_wgt[t * 2 + 1];
    float4 o = *reinterpret_cast<float4*>(out + i);
    float4 a = *reinterpret_cast<const float4*>(y2_buf + (size_t)s0 * Hn + h);
    float4 b = *reinterpret_cast<const float4*>(y2_buf + (size_t)s1 * Hn + h);
    o.x += w0 * a.x + w1 * b.x;
    o.y += w0 * a.y + w1 * b.y;
    o.z += w0 * a.z + w1 * b.z;
    o.w += w0 * a.w + w1 * b.w;
    *reinterpret_cast<float4*>(out + i) = o;
}

// ---------------- launch ----------------
extern "C" void kernel_launch(void* const* d_in, const int* in_sizes, int n_in,
                              void* d_out, int out_size) {
    const float* x    = (const float*)d_in[0];
    const float* Wg_s = (const float*)d_in[1];
    const float* Wu_s = (const float*)d_in[2];
    const float* Wd_s = (const float*)d_in[3];
    const float* Wg   = (const float*)d_in[4];
    const float* Wu   = (const float*)d_in[5];
    const float* Wd   = (const float*)d_in[6];
    const float* Wr   = (const float*)d_in[7];
    float* out = (float*)d_out;

    float *gp, *up, *g2p, *u2p, *y2p, *dlog;
    cudaGetSymbolAddress((void**)&gp,   g_buf);
    cudaGetSymbolAddress((void**)&up,   u_buf);
    cudaGetSymbolAddress((void**)&g2p,  g2_buf);
    cudaGetSymbolAddress((void**)&u2p,  u2_buf);
    cudaGetSymbolAddress((void**)&y2p,  y2_buf);
    cudaGetSymbolAddress((void**)&dlog, dummy_logits);

    bool has_logits = (out_size >= Tn * Hn + Tn * En);
    float* logits = has_logits ? (out + (size_t)Tn * Hn) : dlog;

    // routing pipeline
    init_kernel<<<1, 32>>>();
    routing_kernel<<<Tn / 4, 128>>>(x, Wr, logits);
    prefix_kernel<<<1, 32>>>();
    scatter_kernel<<<Tn / 256, 256>>>();

    // shared expert
    dim3 gGateUp(In / 128, Tn / 128);
    gemm_kernel<false, false><<<gGateUp, 256>>>(x, Wg_s, gp, Tn, In, Hn);
    gemm_kernel<false, false><<<gGateUp, 256>>>(x, Wu_s, up, Tn, In, Hn);
    {
        size_t n4 = (size_t)Tn * In / 4;
        silu_mul_kernel<<<(unsigned)((n4 + 255) / 256), 256>>>(gp, up, n4);
    }
    dim3 gDown(Hn / 128, Tn / 128);
    gemm_kernel<false, false><<<gDown, 256>>>(gp, Wd_s, out, Tn, Hn, In);

    // MoE experts (gathered, compact slots)
    dim3 gMoeGateUp(In / 128, Tn / 128, En);
    gemm_kernel<true, true><<<gMoeGateUp, 256>>>(x, Wg, g2p, Tn, In, Hn);
    gemm_kernel<true, true><<<gMoeGateUp, 256>>>(x, Wu, u2p, Tn, In, Hn);
    {
        size_t n4 = (size_t)2 * Tn * In / 4;
        silu_mul_kernel<<<(unsigned)((n4 + 255) / 256), 256>>>(g2p, u2p, n4);
    }
    dim3 gMoeDown(Hn / 128, Tn / 128, En);
    gemm_kernel<false, true><<<gMoeDown, 256>>>(g2p, Wd, y2p, Tn, Hn, In);

    // final combine
    {
        size_t n4 = (size_t)Tn * Hn / 4;
        combine_kernel<<<(unsigned)((n4 + 255) / 256), 256>>>(out);
    }
}

// round 5
// speedup vs baseline: 3.5373x; 3.5330x over previous
#include <cuda_runtime.h>
#include <cstdint>
#include <math.h>

#define Tn 4096
#define Hn 1024
#define In 2816
#define En 7

// ---------------- static scratch ----------------
__device__ float xr_buf[(size_t)Tn * Hn];
__device__ float wgs_r[(size_t)In * Hn];
__device__ float wus_r[(size_t)In * Hn];
__device__ float wds_r[(size_t)Hn * In];
__device__ float wg_r[(size_t)En * In * Hn];
__device__ float wu_r[(size_t)En * In * Hn];
__device__ float wd_r[(size_t)En * Hn * In];
__device__ float h_buf[(size_t)Tn * In];
__device__ float h2_buf[(size_t)2 * Tn * In];
__device__ float y2_buf[(size_t)2 * Tn * Hn];
__device__ float dummy_logits[(size_t)Tn * En];

__device__ int   d_counts[En];
__device__ int   d_offsets[En];
__device__ int   d_cursor[En];
__device__ int   d_sel[Tn * 2];
__device__ float d_wgt[Tn * 2];
__device__ int   d_slot_token[2 * Tn];
__device__ int   d_token_slot[Tn * 2];

// ---------------- PTX helpers (all portable, sm_80+) ----------------
__device__ __forceinline__ uint32_t smem_u32(const void* p) {
    uint32_t a;
    asm("{ .reg .u64 t; cvta.to.shared.u64 t, %1; cvt.u32.u64 %0, t; }" : "=r"(a) : "l"(p));
    return a;
}
__device__ __forceinline__ float to_tf32(float v) {
    uint32_t r; asm("cvt.rna.tf32.f32 %0, %1;" : "=r"(r) : "f"(v));
    return __uint_as_float(r);
}
__device__ __forceinline__ void cpasync16(uint32_t dst, const void* src) {
    asm volatile("cp.async.cg.shared.global [%0], [%1], 16;" :: "r"(dst), "l"(src) : "memory");
}
__device__ __forceinline__ void cpcommit() {
    asm volatile("cp.async.commit_group;" ::: "memory");
}
__device__ __forceinline__ void cpwait1() {
    asm volatile("cp.async.wait_group 1;" ::: "memory");
}
__device__ __forceinline__ void cpwait0() {
    asm volatile("cp.async.wait_group 0;" ::: "memory");
}

// D(16x8) += A(16x8,row) * B(8x8,col) ; tf32 operands in b32 regs, f32 accum
__device__ __forceinline__ void mma8(float* c, const uint32_t* a, const uint32_t* b) {
    asm volatile(
        "mma.sync.aligned.m16n8k8.row.col.f32.tf32.tf32.f32 "
        "{%0,%1,%2,%3}, {%4,%5,%6,%7}, {%8,%9}, {%0,%1,%2,%3};\n"
        : "+f"(c[0]), "+f"(c[1]), "+f"(c[2]), "+f"(c[3])
        : "r"(a[0]), "r"(a[1]), "r"(a[2]), "r"(a[3]),
          "r"(b[0]), "r"(b[1]));
}

// ---------------- small kernels ----------------
__global__ void init_kernel() {
    int i = threadIdx.x;
    if (i < En) { d_counts[i] = 0; d_cursor[i] = 0; }
}

__global__ void round_kernel(const float* __restrict__ s, float* __restrict__ d, size_t n4) {
    size_t i = (size_t)blockIdx.x * blockDim.x + threadIdx.x;
    if (i >= n4) return;
    float4 v = reinterpret_cast<const float4*>(s)[i];
    v.x = to_tf32(v.x); v.y = to_tf32(v.y); v.z = to_tf32(v.z); v.w = to_tf32(v.w);
    reinterpret_cast<float4*>(d)[i] = v;
}

__global__ void routing_kernel(const float* __restrict__ x,
                               const float* __restrict__ Wr,
                               float* __restrict__ logits_out,
                               float* __restrict__ xr) {
    int warp = threadIdx.x >> 5;
    int lane = threadIdx.x & 31;
    int t = blockIdx.x * (blockDim.x >> 5) + warp;
    if (t >= Tn) return;
    const float* xrow = x + (size_t)t * Hn;
    float acc[En];
#pragma unroll
    for (int e = 0; e < En; e++) acc[e] = 0.f;
    for (int k = lane; k < Hn; k += 32) {
        float xv = xrow[k];
        xr[(size_t)t * Hn + k] = to_tf32(xv);
#pragma unroll
        for (int e = 0; e < En; e++) acc[e] += xv * Wr[e * Hn + k];
    }
#pragma unroll
    for (int e = 0; e < En; e++) {
#pragma unroll
        for (int o = 16; o > 0; o >>= 1)
            acc[e] += __shfl_xor_sync(0xFFFFFFFFu, acc[e], o);
    }
    if (lane == 0) {
        int b0 = 0; float v0 = acc[0];
#pragma unroll
        for (int e = 1; e < En; e++) if (acc[e] > v0) { v0 = acc[e]; b0 = e; }
        int b1 = -1; float v1 = -1e30f;
#pragma unroll
        for (int e = 0; e < En; e++)
            if (e != b0 && acc[e] > v1) { v1 = acc[e]; b1 = e; }
        float w0 = 1.f / (1.f + expf(v1 - v0));
        float w1 = 1.f - w0;
        d_sel[t * 2 + 0] = b0; d_sel[t * 2 + 1] = b1;
        d_wgt[t * 2 + 0] = w0; d_wgt[t * 2 + 1] = w1;
        atomicAdd(&d_counts[b0], 1);
        atomicAdd(&d_counts[b1], 1);
#pragma unroll
        for (int e = 0; e < En; e++) logits_out[(size_t)t * En + e] = acc[e];
    }
}

__global__ void prefix_kernel() {
    if (threadIdx.x == 0) {
        int s = 0;
        for (int e = 0; e < En; e++) { d_offsets[e] = s; s += d_counts[e]; }
    }
}

__global__ void scatter_kernel() {
    int t = blockIdx.x * blockDim.x + threadIdx.x;
    if (t >= Tn) return;
#pragma unroll
    for (int k = 0; k < 2; k++) {
        int e = d_sel[t * 2 + k];
        int p = atomicAdd(&d_cursor[e], 1);
        int slot = d_offsets[e] + p;
        d_slot_token[slot] = t;
        d_token_slot[t * 2 + k] = slot;
    }
}

__global__ void combine_kernel(float* __restrict__ out) {
    size_t idx = (size_t)blockIdx.x * blockDim.x + threadIdx.x;
    size_t i = idx * 4;
    if (i >= (size_t)Tn * Hn) return;
    int t = (int)(i / Hn);
    int h = (int)(i % Hn);
    int s0 = d_token_slot[t * 2 + 0];
    int s1 = d_token_slot[t * 2 + 1];
    float w0 = d_wgt[t * 2 + 0];
    float w1 = d_wgt[t * 2 + 1];
    float4 o = *reinterpret_cast<float4*>(out + i);
    float4 a = *reinterpret_cast<const float4*>(y2_buf + (size_t)s0 * Hn + h);
    float4 b = *reinterpret_cast<const float4*>(y2_buf + (size_t)s1 * Hn + h);
    o.x += w0 * a.x + w1 * b.x;
    o.y += w0 * a.y + w1 * b.y;
    o.z += w0 * a.z + w1 * b.z;
    o.w += w0 * a.w + w1 * b.w;
    *reinterpret_cast<float4*>(out + i) = o;
}

// ---------------- mma.sync tf32 GEMM ----------------
// C[M,N] = A[M,K] @ W[N,K]^T. CTA tile 128x128, BK=32, 256 thr (8 warps),
// warp tile 64x32 (2x4 warp grid), mma m16n8k8, cp.async double buffer.
// smem tiles stored [row][k] with row stride 36 floats (conflict-free frags).
// FUSED: two weight matrices (gate,up), epilogue writes silu(g)*u (tf32-rounded).
// GATHER: A row via d_slot_token. EXPERT: segment + per-expert weight offset.
#define TSTR 36
#define TFL (128 * TSTR)          // floats per smem tile

template <bool FUSED, bool GATHER, bool EXPERT, bool ROUND_OUT>
__global__ void __launch_bounds__(256, 1)
mma_gemm(const float* __restrict__ A, const float* __restrict__ W0,
         const float* __restrict__ W1, float* __restrict__ C, int K, int ldC) {
    int rowBase = 0, segRows = Tn;
    const float* W0p = W0;
    const float* W1p = W1;
    if (EXPERT) {
        int e = blockIdx.z;
        rowBase = d_offsets[e];
        segRows = d_counts[e];
        size_t ws = (size_t)ldC * K;
        W0p = W0 + (size_t)e * ws;
        if (FUSED) W1p = W1 + (size_t)e * ws;
    }
    int byRow = blockIdx.y * 128;
    if (byRow >= segRows) return;
    int bx = blockIdx.x * 128;

    extern __shared__ float sm[];
    const int NOP = FUSED ? 3 : 2;

    int tid = threadIdx.x;
    int lane = tid & 31, wid = tid >> 5;
    int gid = lane >> 2, tig = lane & 3;
    int wm = wid & 1, wn = wid >> 1;

    // ---- global->smem mapping: thread handles rows (tid>>3)+r*32, q=(tid&7) float4
    int lrow_ = tid >> 3;
    int q_ = tid & 7;
    uint32_t dstW = (uint32_t)(lrow_ * TSTR + q_ * 4);   // float index in tile

    const float* aP[4];
#pragma unroll
    for (int r = 0; r < 4; r++) {
        int lrow = byRow + lrow_ + r * 32;
        int lcl = lrow < segRows ? lrow : (segRows - 1);
        int arow = GATHER ? d_slot_token[rowBase + lcl] : (rowBase + lcl);
        aP[r] = A + (size_t)arow * K + q_ * 4;
    }
    const float* w0B = W0p + (size_t)(bx + lrow_) * K + q_ * 4;
    const float* w1B = FUSED ? (W1p + (size_t)(bx + lrow_) * K + q_ * 4) : nullptr;

    uint32_t sA = smem_u32(sm);

    float acc0[4][4][4];
    float acc1[4][4][4];
#pragma unroll
    for (int mi = 0; mi < 4; mi++)
#pragma unroll
        for (int ni = 0; ni < 4; ni++)
#pragma unroll
            for (int r = 0; r < 4; r++) { acc0[mi][ni][r] = 0.f; if (FUSED) acc1[mi][ni][r] = 0.f; }

    auto loadStage = [&](int j) {
        uint32_t st = sA + (uint32_t)(j & 1) * (uint32_t)(NOP * TFL * 4);
        size_t koff = (size_t)j * 32;
#pragma unroll
        for (int r = 0; r < 4; r++)
            cpasync16(st + (dstW + r * 32 * TSTR) * 4, aP[r] + koff);
#pragma unroll
        for (int r = 0; r < 4; r++)
            cpasync16(st + TFL * 4 + (dstW + r * 32 * TSTR) * 4, w0B + (size_t)(r * 32) * K + koff);
        if (FUSED) {
#pragma unroll
            for (int r = 0; r < 4; r++)
                cpasync16(st + 2 * TFL * 4 + (dstW + r * 32 * TSTR) * 4, w1B + (size_t)(r * 32) * K + koff);
        }
        cpcommit();
    };

    int NKS = K / 32;
    loadStage(0);

    for (int i = 0; i < NKS; i++) {
        if (i + 1 < NKS) { loadStage(i + 1); cpwait1(); }
        else             { cpwait0(); }
        __syncthreads();

        const float* base = sm + (size_t)(i & 1) * NOP * TFL;
        const float* As = base;
        const float* B0s = base + TFL;
        const float* B1s = base + 2 * TFL;

#pragma unroll
        for (int kk = 0; kk < 4; kk++) {
            int k0 = kk * 8;
            uint32_t a[4][4];
#pragma unroll
            for (int mi = 0; mi < 4; mi++) {
                const float* ap = As + (wm * 64 + mi * 16 + gid) * TSTR + k0 + tig;
                a[mi][0] = __float_as_uint(ap[0]);
                a[mi][2] = __float_as_uint(ap[4]);
                a[mi][1] = __float_as_uint(ap[8 * TSTR]);
                a[mi][3] = __float_as_uint(ap[8 * TSTR + 4]);
            }
            uint32_t b[4][2];
#pragma unroll
            for (int ni = 0; ni < 4; ni++) {
                const float* bp = B0s + (wn * 32 + ni * 8 + gid) * TSTR + k0 + tig;
                b[ni][0] = __float_as_uint(bp[0]);
                b[ni][1] = __float_as_uint(bp[4]);
            }
#pragma unroll
            for (int mi = 0; mi < 4; mi++)
#pragma unroll
                for (int ni = 0; ni < 4; ni++)
                    mma8(acc0[mi][ni], a[mi], b[ni]);
            if (FUSED) {
#pragma unroll
                for (int ni = 0; ni < 4; ni++) {
                    const float* bp = B1s + (wn * 32 + ni * 8 + gid) * TSTR + k0 + tig;
                    b[ni][0] = __float_as_uint(bp[0]);
                    b[ni][1] = __float_as_uint(bp[4]);
                }
#pragma unroll
                for (int mi = 0; mi < 4; mi++)
#pragma unroll
                    for (int ni = 0; ni < 4; ni++)
                        mma8(acc1[mi][ni], a[mi], b[ni]);
            }
        }
        __syncthreads();
    }

    // ---- epilogue ----
#pragma unroll
    for (int mi = 0; mi < 4; mi++) {
        int lr0 = byRow + wm * 64 + mi * 16 + gid;
#pragma unroll
        for (int half = 0; half < 2; half++) {
            int lr = lr0 + half * 8;
            if (lr < segRows) {
                float* cp = C + (size_t)(rowBase + lr) * ldC + bx + wn * 32 + 2 * tig;
#pragma unroll
                for (int ni = 0; ni < 4; ni++) {
                    float v0 = acc0[mi][ni][half * 2 + 0];
                    float v1 = acc0[mi][ni][half * 2 + 1];
                    if (FUSED) {
                        float u0 = acc1[mi][ni][half * 2 + 0];
                        float u1 = acc1[mi][ni][half * 2 + 1];
                        v0 = v0 / (1.f + expf(-v0)) * u0;
                        v1 = v1 / (1.f + expf(-v1)) * u1;
                    }
                    if (ROUND_OUT) { v0 = to_tf32(v0); v1 = to_tf32(v1); }
                    *reinterpret_cast<float2*>(cp + ni * 8) = make_float2(v0, v1);
                }
            }
        }
    }
}

// ---------------- launch ----------------
extern "C" void kernel_launch(void* const* d_in, const int* in_sizes, int n_in,
                              void* d_out, int out_size) {
    const float* x    = (const float*)d_in[0];
    const float* Wg_s = (const float*)d_in[1];
    const float* Wu_s = (const float*)d_in[2];
    const float* Wd_s = (const float*)d_in[3];
    const float* Wg   = (const float*)d_in[4];
    const float* Wu   = (const float*)d_in[5];
    const float* Wd   = (const float*)d_in[6];
    const float* Wr   = (const float*)d_in[7];
    float* out = (float*)d_out;

    float *xr, *gsr, *usr, *dsr, *gr, *ur, *dr, *hp, *h2p, *y2p, *dlog;
    cudaGetSymbolAddress((void**)&xr,  xr_buf);
    cudaGetSymbolAddress((void**)&gsr, wgs_r);
    cudaGetSymbolAddress((void**)&usr, wus_r);
    cudaGetSymbolAddress((void**)&dsr, wds_r);
    cudaGetSymbolAddress((void**)&gr,  wg_r);
    cudaGetSymbolAddress((void**)&ur,  wu_r);
    cudaGetSymbolAddress((void**)&dr,  wd_r);
    cudaGetSymbolAddress((void**)&hp,  h_buf);
    cudaGetSymbolAddress((void**)&h2p, h2_buf);
    cudaGetSymbolAddress((void**)&y2p, y2_buf);
    cudaGetSymbolAddress((void**)&dlog, dummy_logits);

    bool has_logits = (out_size >= Tn * Hn + Tn * En);
    float* logits = has_logits ? (out + (size_t)Tn * Hn) : dlog;

    const int SMF = 2 * 3 * TFL * 4;   // fused: 2 stages x (A, Wg, Wu)  = 110592 B
    const int SMD = 2 * 2 * TFL * 4;   // down:  2 stages x (A, W)       =  73728 B
    cudaFuncSetAttribute(mma_gemm<true,  false, false, true >, cudaFuncAttributeMaxDynamicSharedMemorySize, SMF);
    cudaFuncSetAttribute(mma_gemm<true,  true,  true,  true >, cudaFuncAttributeMaxDynamicSharedMemorySize, SMF);
    cudaFuncSetAttribute(mma_gemm<false, false, false, false>, cudaFuncAttributeMaxDynamicSharedMemorySize, SMD);
    cudaFuncSetAttribute(mma_gemm<false, false, true,  false>, cudaFuncAttributeMaxDynamicSharedMemorySize, SMD);

    // tf32 pre-rounding of weights (x rounded inside routing_kernel)
    auto roundN = [&](const float* s, float* d, size_t n) {
        size_t n4 = n / 4;
        round_kernel<<<(unsigned)((n4 + 255) / 256), 256>>>(s, d, n4);
    };
    roundN(Wg_s, gsr, (size_t)In * Hn);
    roundN(Wu_s, usr, (size_t)In * Hn);
    roundN(Wd_s, dsr, (size_t)Hn * In);
    roundN(Wg,   gr,  (size_t)En * In * Hn);
    roundN(Wu,   ur,  (size_t)En * In * Hn);
    roundN(Wd,   dr,  (size_t)En * Hn * In);

    // routing pipeline
    init_kernel<<<1, 32>>>();
    routing_kernel<<<Tn / 4, 128>>>(x, Wr, logits, xr);
    prefix_kernel<<<1, 32>>>();
    scatter_kernel<<<Tn / 256, 256>>>();

    // shared expert: fused gate+up -> h ; down -> out
    mma_gemm<true, false, false, true><<<dim3(In / 128, Tn / 128, 1), 256, SMF>>>(
        xr, gsr, usr, hp, Hn, In);
    mma_gemm<false, false, false, false><<<dim3(Hn / 128, Tn / 128, 1), 256, SMD>>>(
        hp, dsr, nullptr, out, In, Hn);

    // MoE: fused gathered gate+up -> h2 ; down -> y2 (per slot, unscaled)
    mma_gemm<true, true, true, true><<<dim3(In / 128, Tn / 128, En), 256, SMF>>>(
        xr, gr, ur, h2p, Hn, In);
    mma_gemm<false, false, true, false><<<dim3(Hn / 128, Tn / 128, En), 256, SMD>>>(
        h2p, dr, nullptr, y2p, In, Hn);

    // combine: out += w0*y2[s0] + w1*y2[s1]
    size_t n4 = (size_t)Tn * Hn / 4;
    combine_kernel<<<(unsigned)((n4 + 255) / 256), 256>>>(out);
}